// round 12
// baseline (speedup 1.0000x reference)
#include <cuda_runtime.h>
#include <cuda_bf16.h>
#include <math.h>
#include <stdint.h>

#define BB 4
#define NN 4096
#define FF 128
#define SS 1024
#define KK 64
#define CC 256
#define MTOT (BB*SS*KK)
#define EPSF 1e-5f

// ---------------- device scratch ----------------
__device__ int   g_cent[BB*SS];
__device__ int   g_group[BB*SS*KK];
__device__ float g_P[BB*NN*CC];
__device__ float g_Q[BB*SS*CC];
__device__ float g_W1sumT[FF*CC];
__device__ float g_W1AT[FF*CC];
__device__ float g_W2rt[CC*CC];
__device__ float g_sum1[CC], g_sq1[CC], g_sum2[CC], g_sq2[CC];
__device__ float g_mx[BB*SS*CC], g_mn[BB*SS*CC];

__device__ __forceinline__ float to_tf32(float x){
    unsigned u;
    asm("cvt.rna.tf32.f32 %0, %1;" : "=r"(u) : "f"(x));
    return __uint_as_float(u);
}
// packed f32x2 helpers (per-component rounding == scalar FADD/FMUL/FFMA)
__device__ __forceinline__ unsigned long long pk2(float lo, float hi){
    unsigned long long r;
    asm("mov.b64 %0, {%1,%2};" : "=l"(r) : "f"(lo), "f"(hi));
    return r;
}
__device__ __forceinline__ void upk2(unsigned long long v, float& lo, float& hi){
    asm("mov.b64 {%0,%1}, %2;" : "=f"(lo), "=f"(hi) : "l"(v));
}
__device__ __forceinline__ unsigned long long add2(unsigned long long a, unsigned long long b){
    unsigned long long r; asm("add.rn.f32x2 %0,%1,%2;" : "=l"(r) : "l"(a), "l"(b)); return r;
}
__device__ __forceinline__ unsigned long long mul2(unsigned long long a, unsigned long long b){
    unsigned long long r; asm("mul.rn.f32x2 %0,%1,%2;" : "=l"(r) : "l"(a), "l"(b)); return r;
}
__device__ __forceinline__ unsigned long long fma2(unsigned long long a, unsigned long long b, unsigned long long c){
    unsigned long long r; asm("fma.rn.f32x2 %0,%1,%2,%3;" : "=l"(r) : "l"(a), "l"(b), "l"(c)); return r;
}

// ---------------- prep ----------------
__global__ void k_prep(const float* __restrict__ W1, const float* __restrict__ W2){
    int idx = blockIdx.x*256 + threadIdx.x;
    if (idx < FF*CC){
        int c = idx / CC, o = idx % CC;
        float a = to_tf32(W1[o*(2*FF)+c]);
        float bwt = to_tf32(W1[o*(2*FF)+FF+c]);
        g_W1sumT[idx] = a + bwt;
        g_W1AT[idx]   = a;
    }
    if (idx < CC*CC){
        g_W2rt[idx] = to_tf32(W2[idx]);
    }
    if (idx < CC){
        g_sum1[idx]=0.f; g_sq1[idx]=0.f; g_sum2[idx]=0.f; g_sq2[idx]=0.f;
    }
}

// ---------------- mega1 (512 threads): FPS (4 blocks) || pgemm (1024 blocks) ----------------
extern __shared__ char mega_smem[];

__device__ void fps_body(const float* __restrict__ pos, int b){
    // layout: slots[2][16] u64 (256B) | final[2] u32 (+pad 32B) | s_pos | s_sel | s_mask
    unsigned long long* slots = (unsigned long long*)mega_smem;
    unsigned* sfinal = (unsigned*)(mega_smem + 256);
    float*    s_pos  = (float*)(mega_smem + 288);
    int*      s_sel  = (int*)(mega_smem + 288 + NN*3*4);
    unsigned* s_mask = (unsigned*)(mega_smem + 288 + NN*3*4 + SS*4);
    volatile unsigned long long* vslots = (volatile unsigned long long*)slots;
    volatile unsigned* vfinal = (volatile unsigned*)sfinal;
    int t = threadIdx.x;
    const float* bp = pos + (size_t)b*NN*3;

    for (int i=t; i<NN*3; i+=512) s_pos[i] = bp[i];
    if (t < 32) slots[t] = 0ull;
    if (t < 2)  sfinal[t] = 0u;
    if (t==0) s_sel[0] = 0;
    __syncthreads();

    unsigned long long px2[4], py2[4], pz2[4];
    float dd[8];
    float qx=s_pos[0], qy=s_pos[1], qz=s_pos[2];
    float vmaxf = 0.f;
#pragma unroll
    for (int jp=0;jp<4;jp++){
        int i0 = t + 512*(2*jp), i1 = t + 512*(2*jp+1);
        float x0=s_pos[3*i0], y0=s_pos[3*i0+1], z0=s_pos[3*i0+2];
        float x1=s_pos[3*i1], y1=s_pos[3*i1+1], z1=s_pos[3*i1+2];
        px2[jp]=pk2(x0,x1); py2[jp]=pk2(y0,y1); pz2[jp]=pk2(z0,z1);
        float dx0=x0-qx, dy0=y0-qy, dz0=z0-qz;
        float dx1=x1-qx, dy1=y1-qy, dz1=z1-qz;
        dd[2*jp]   = dx0*dx0 + dy0*dy0 + dz0*dz0;
        dd[2*jp+1] = dx1*dx1 + dy1*dy1 + dz1*dz1;
        vmaxf = fmaxf(vmaxf, fmaxf(dd[2*jp], dd[2*jp+1]));
    }

    int wid = t >> 5, lane = t & 31;
#pragma unroll 1
    for (int it=1; it<SS; it++){
        unsigned tag = (unsigned)it & 0x3FFu;
        int par = it & 1;
        unsigned ub = __float_as_uint(vmaxf);            // dists >= 0: bits order-monotone
        unsigned rv = __reduce_max_sync(0xffffffffu, ub);
        unsigned cand = 0u;
        if (ub == rv){
            int idx = 0;
#pragma unroll
            for (int j=7;j>=0;j--)
                if (__float_as_uint(dd[j]) == rv) idx = t + 512*j;   // ends at smallest j
            cand = 0xFFFu & ~(unsigned)idx;
        }
        unsigned ri = __reduce_max_sync(0xffffffffu, cand);  // max ~idx == min idx
        if (lane==0)
            vslots[par*16 + wid] = ((unsigned long long)rv << 22)
                                 | ((unsigned long long)ri << 10)
                                 | (unsigned long long)tag;
        // warp 0: lanes 0-15 poll one slot each in parallel, reduce, publish final
        if (wid==0 && lane<16){
            unsigned long long v;
            do { v = vslots[par*16 + lane]; } while ((unsigned)(v & 0x3FFull) != tag);
            unsigned val = (unsigned)(v >> 22);
            unsigned rid = (unsigned)((v >> 10) & 0xFFFull);
            unsigned mv = __reduce_max_sync(0xFFFFu, val);
            unsigned c2 = (val==mv) ? rid : 0u;
            unsigned mi = __reduce_max_sync(0xFFFFu, c2);
            if (lane==0) vfinal[par] = (mi << 10) | tag;
        }
        unsigned fv;
        do { fv = vfinal[par]; } while ((fv & 0x3FFu) != tag);
        int nxt = (int)(0xFFFu & ~(fv >> 10));
        if (t==0) s_sel[it] = nxt;
        float cx=s_pos[3*nxt], cy=s_pos[3*nxt+1], cz=s_pos[3*nxt+2];
        unsigned long long ncx=pk2(-cx,-cx), ncy=pk2(-cy,-cy), ncz=pk2(-cz,-cz);
        float nv = 0.f;
#pragma unroll
        for (int jp=0;jp<4;jp++){
            unsigned long long dx2=add2(px2[jp],ncx);
            unsigned long long dy2=add2(py2[jp],ncy);
            unsigned long long dz2=add2(pz2[jp],ncz);
            unsigned long long d2 = mul2(dx2,dx2);
            d2 = fma2(dy2,dy2,d2);
            d2 = fma2(dz2,dz2,d2);
            float dlo,dhi; upk2(d2,dlo,dhi);
            float a = fminf(dd[2*jp],   dlo);
            float c = fminf(dd[2*jp+1], dhi);
            dd[2*jp]=a; dd[2*jp+1]=c;
            nv = fmaxf(nv, fmaxf(a,c));
        }
        vmaxf = nv;
    }
    __syncthreads();
    if (t < NN/32) s_mask[t]=0u;
    __syncthreads();
    for (int i=t; i<SS; i+=512) atomicOr(&s_mask[s_sel[i]>>5], 1u<<(s_sel[i]&31));
    __syncthreads();
    for (int i=t; i<SS; i+=512){
        int idx=s_sel[i];
        int w=idx>>5, r=0;
        for (int ww=0; ww<w; ww++) r += __popc(s_mask[ww]);
        r += __popc(s_mask[w] & ((1u<<(idx&31))-1u));
        g_cent[b*SS + r] = idx;
    }
}

__device__ void pgemm_body(const float* __restrict__ feat, int blk){
    float (*sf)[FF] = (float (*)[FF])mega_smem;
    int r0 = blk*16, t = threadIdx.x;
    for (int i=t; i<16*FF; i+=512)
        sf[i/FF][i%FF] = to_tf32(feat[(size_t)(r0 + i/FF)*FF + (i%FF)]);
    __syncthreads();
    int h = t >> 8;          // row half: 0 or 1
    int o = t & 255;         // channel
    float acc[8];
#pragma unroll
    for (int r=0;r<8;r++) acc[r]=0.f;
    for (int c=0;c<FF;c++){
        float w = g_W1sumT[c*CC + o];
#pragma unroll
        for (int r=0;r<8;r++) acc[r]=fmaf(sf[h*8+r][c], w, acc[r]);
    }
#pragma unroll
    for (int r=0;r<8;r++) g_P[(size_t)(r0 + h*8 + r)*CC + o] = acc[r];
}

__global__ __launch_bounds__(512) void k_mega1(const float* __restrict__ pos,
                                               const float* __restrict__ feat){
    if (blockIdx.x < 4) fps_body(pos, blockIdx.x);
    else                pgemm_body(feat, blockIdx.x - 4);
}

// ---------------- KNN (256 thr, privatized hist) + fused BN1 stats ----------------
__global__ __launch_bounds__(256) void k_knns(const float* __restrict__ pos,
                                              const float* __restrict__ b1){
    __shared__ unsigned sbits[NN];
    __shared__ int shist[2][256];
    __shared__ unsigned s_prefix;
    __shared__ int s_want, s_cnt, s_eqcnt;
    __shared__ int s_eq[256];
    __shared__ int s_g[KK];
    int q = blockIdx.x, t = threadIdx.x;
    int b = q / SS;
    int c = g_cent[q];
    int half = t >> 7;
    const float* bp = pos + (size_t)b*NN*3;
    float qx=bp[3*c], qy=bp[3*c+1], qz=bp[3*c+2];
    float qq = __fadd_rn(__fadd_rn(__fmul_rn(qx,qx), __fmul_rn(qy,qy)), __fmul_rn(qz,qz));

    for (int i=t; i<NN; i+=256){
        float x=bp[3*i], y=bp[3*i+1], z=bp[3*i+2];
        float pp = __fadd_rn(__fadd_rn(__fmul_rn(x,x), __fmul_rn(y,y)), __fmul_rn(z,z));
        float dot = __fadd_rn(__fadd_rn(__fmul_rn(qx,x), __fmul_rn(qy,y)), __fmul_rn(qz,z));
        float d = __fadd_rn(__fadd_rn(__fmul_rn(-2.0f, dot), qq), pp);
        unsigned u = __float_as_uint(d);
        u = (u & 0x80000000u) ? ~u : (u | 0x80000000u);
        sbits[i] = u;
    }
    if (t==0){ s_prefix=0u; s_want=KK; s_cnt=0; s_eqcnt=0; }
    __syncthreads();

    for (int pass=0; pass<4; pass++){
        int shift = 24 - 8*pass;
        shist[0][t]=0; shist[1][t]=0;
        __syncthreads();
        unsigned pref = s_prefix;
        for (int i=t; i<NN; i+=256){
            unsigned u = sbits[i];
            bool m = (pass==0) || ((u >> (shift+8)) == pref);
            if (m) atomicAdd(&shist[half][(u>>shift)&0xFFu], 1);
        }
        __syncthreads();
        if (t==0){
            int want=s_want, cum=0, bin;
            for (bin=0; bin<256; bin++){
                int h=shist[0][bin]+shist[1][bin];
                if (cum+h >= want) break;
                cum += h;
            }
            s_want = want - cum;
            s_prefix = (s_prefix<<8) | (unsigned)bin;
        }
        __syncthreads();
    }
    unsigned T = s_prefix;
    for (int i=t; i<NN; i+=256){
        unsigned u = sbits[i];
        if (u < T){
            int p = atomicAdd(&s_cnt,1);
            g_group[q*KK + p] = i;
            s_g[p] = i;
        } else if (u == T){
            int p = atomicAdd(&s_eqcnt,1);
            if (p < 256) s_eq[p] = i;
        }
    }
    __syncthreads();
    if (t==0){
        int base = s_cnt;
        int nd   = KK - base;
        int ec   = s_eqcnt;
        if (ec <= 256){
            for (int r=0; r<nd; r++){
                int mi=r;
                for (int j=r+1; j<ec; j++) if (s_eq[j] < s_eq[mi]) mi=j;
                int tmp=s_eq[r]; s_eq[r]=s_eq[mi]; s_eq[mi]=tmp;
                g_group[q*KK + base + r] = s_eq[r];
                s_g[base + r] = s_eq[r];
            }
        } else {
            int w=nd, p=base;
            for (int i=0; i<NN && w>0; i++)
                if (sbits[i]==T){ g_group[q*KK + p] = i; s_g[p] = i; p++; w--; }
        }
    }
    __syncthreads();
    // fused BN1 stats: 256 threads, one channel each
    int o = t;
    float base = b1[o] - g_Q[(size_t)q*CC + o];
    float sum=0.f, sq=0.f;
    const float* Pb = g_P + (size_t)b*NN*CC;
#pragma unroll 4
    for (int k=0;k<KK;k++){
        float h = Pb[(size_t)s_g[k]*CC + o] + base;
        sum += h; sq = fmaf(h,h,sq);
    }
    atomicAdd(&g_sum1[o], sum);
    atomicAdd(&g_sq1[o],  sq);
}

// ---------------- Q = tf32(centroid feat) @ W1AT ----------------
__global__ __launch_bounds__(256) void k_qgemm(const float* __restrict__ feat){
    __shared__ float sf[16][FF];
    int r0 = blockIdx.x*16, t = threadIdx.x;
    for (int i=t; i<16*FF; i+=256){
        int rr = r0 + i/FF;
        int b  = rr / SS;
        int cent = g_cent[rr];
        sf[i/FF][i%FF] = to_tf32(feat[(size_t)(b*NN + cent)*FF + (i%FF)]);
    }
    __syncthreads();
    int o = t;
    float acc[16];
#pragma unroll
    for (int r=0;r<16;r++) acc[r]=0.f;
    for (int c=0;c<FF;c++){
        float w = g_W1AT[c*CC + o];
#pragma unroll
        for (int r=0;r<16;r++) acc[r]=fmaf(sf[r][c], w, acc[r]);
    }
#pragma unroll
    for (int r=0;r<16;r++) g_Q[(size_t)(r0+r)*CC + o] = acc[r];
}

// ---------------- layer2 GEMM via mma.sync tf32 (R7 config) ----------------
#define ASTR 36
extern __shared__ float dyn_smem[];
__global__ __launch_bounds__(256, 1) void k_gemm2m(const float* __restrict__ b1,
                                                   const float* __restrict__ gamma1,
                                                   const float* __restrict__ beta1,
                                                   const float* __restrict__ b2){
    __shared__ float a_s[CC];
    __shared__ float d_s[2*CC];
    __shared__ int   s_nbr[128];

    float* As = dyn_smem;             // [128][ASTR]
    float* Bs = dyn_smem + 128*ASTR;  // [256][ASTR]

    int t = threadIdx.x;
    int bid = blockIdx.x;
    int q0 = 2*bid;
    int batch = q0 >> 10;

    if (t < 128) s_nbr[t] = g_group[bid*128 + t];
    {
        int c = t;
        float mean = g_sum1[c]*(1.0f/MTOT);
        float var  = g_sq1[c]*(1.0f/MTOT) - mean*mean;
        float a    = gamma1[c]*rsqrtf(var + EPSF);
        float ccv  = beta1[c] - mean*a;
        a_s[c] = a;
        d_s[c]    = fmaf(a, b1[c] - g_Q[(size_t)q0*CC + c], ccv);
        d_s[CC+c] = fmaf(a, b1[c] - g_Q[(size_t)(q0+1)*CC + c], ccv);
    }

    int lane = t & 31, wid = t >> 5;
    int warpM = wid >> 2, warpN = wid & 3;
    int r0 = warpM*64, n0 = warpN*64;
    int g = lane >> 2, tig = lane & 3;

    float acc[4][8][4];
#pragma unroll
    for (int mt=0;mt<4;mt++)
#pragma unroll
        for (int nt=0;nt<8;nt++)
#pragma unroll
            for (int i=0;i<4;i++) acc[mt][nt][i]=0.f;

    const uint32_t* Ab = (const uint32_t*)As + (r0+g)*ASTR + tig;
    const uint32_t* Bb = (const uint32_t*)Bs + (n0+g)*ASTR + tig;

    int am = t >> 1;
    int aj0 = (t & 1) * 16;
    int agrp = am >> 6;
    __syncthreads();
    int nbr = s_nbr[am];
    const float* Pr = g_P + ((size_t)(batch*NN + nbr))*CC;

#pragma unroll 1
    for (int kc=0; kc<8; kc++){
        if (kc > 0) __syncthreads();
        {
            const float* dv = d_s + agrp*CC + kc*32 + aj0;
            const float* av = a_s + kc*32 + aj0;
            const float* pr = Pr + kc*32 + aj0;
            float* arow = As + am*ASTR + aj0;
#pragma unroll
            for (int i=0;i<4;i++){
                float4 p = *(const float4*)(pr + 4*i);
                float4 v;
                v.x = to_tf32(fmaxf(fmaf(av[4*i+0], p.x, dv[4*i+0]), 0.f));
                v.y = to_tf32(fmaxf(fmaf(av[4*i+1], p.y, dv[4*i+1]), 0.f));
                v.z = to_tf32(fmaxf(fmaf(av[4*i+2], p.z, dv[4*i+2]), 0.f));
                v.w = to_tf32(fmaxf(fmaf(av[4*i+3], p.w, dv[4*i+3]), 0.f));
                *(float4*)(arow + 4*i) = v;
            }
        }
        {
            const float* wr = g_W2rt + (size_t)t*CC + kc*32;
            float* brow = Bs + t*ASTR;
#pragma unroll
            for (int i=0;i<8;i++)
                *(float4*)(brow + 4*i) = *(const float4*)(wr + 4*i);
        }
        __syncthreads();
#pragma unroll
        for (int kk=0; kk<4; kk++){
            int kb = kk*8;
            uint32_t af[4][4];
#pragma unroll
            for (int mt=0;mt<4;mt++){
                af[mt][0] = Ab[(mt*16    )*ASTR + kb];
                af[mt][1] = Ab[(mt*16 + 8)*ASTR + kb];
                af[mt][2] = Ab[(mt*16    )*ASTR + kb + 4];
                af[mt][3] = Ab[(mt*16 + 8)*ASTR + kb + 4];
            }
            uint32_t bf[8][2];
#pragma unroll
            for (int nt=0;nt<8;nt++){
                bf[nt][0] = Bb[(nt*8)*ASTR + kb];
                bf[nt][1] = Bb[(nt*8)*ASTR + kb + 4];
            }
#pragma unroll
            for (int mt=0;mt<4;mt++){
#pragma unroll
                for (int nt=0;nt<8;nt++){
                    asm volatile(
                        "mma.sync.aligned.m16n8k8.row.col.f32.tf32.tf32.f32 "
                        "{%0,%1,%2,%3}, {%4,%5,%6,%7}, {%8,%9}, {%0,%1,%2,%3};"
                        : "+f"(acc[mt][nt][0]), "+f"(acc[mt][nt][1]),
                          "+f"(acc[mt][nt][2]), "+f"(acc[mt][nt][3])
                        : "r"(af[mt][0]), "r"(af[mt][1]), "r"(af[mt][2]), "r"(af[mt][3]),
                          "r"(bf[nt][0]), "r"(bf[nt][1]));
                }
            }
        }
    }

    int q = q0 + warpM;
#pragma unroll
    for (int nt=0; nt<8; nt++){
#pragma unroll
        for (int hc=0; hc<2; hc++){
            int col = n0 + nt*8 + 2*tig + hc;
            float bias = __ldg(&b2[col]);
            float mx=-3.402823466e38f, mn=3.402823466e38f, sum=0.f, sq=0.f;
#pragma unroll
            for (int mt=0;mt<4;mt++){
                float h0 = acc[mt][nt][hc]   + bias;
                float h1 = acc[mt][nt][2+hc] + bias;
                mx=fmaxf(mx,fmaxf(h0,h1)); mn=fminf(mn,fminf(h0,h1));
                sum += h0 + h1; sq = fmaf(h0,h0,sq); sq = fmaf(h1,h1,sq);
            }
#pragma unroll
            for (int off=4; off<=16; off<<=1){
                mx  = fmaxf(mx,  __shfl_xor_sync(0xffffffffu, mx,  off));
                mn  = fminf(mn,  __shfl_xor_sync(0xffffffffu, mn,  off));
                sum = sum +      __shfl_xor_sync(0xffffffffu, sum, off);
                sq  = sq +       __shfl_xor_sync(0xffffffffu, sq,  off);
            }
            if (g == 0){
                g_mx[(size_t)q*CC + col] = mx;
                g_mn[(size_t)q*CC + col] = mn;
                atomicAdd(&g_sum2[col], sum);
                atomicAdd(&g_sq2[col],  sq);
            }
        }
    }
}

// ---------------- BN2 + ReLU + maxpool + outputs ----------------
__global__ __launch_bounds__(256) void k_out(const float* __restrict__ pos,
                                             const float* __restrict__ gamma2,
                                             const float* __restrict__ beta2,
                                             float* __restrict__ out){
    int q = blockIdx.x, t = threadIdx.x, b = q/SS;
    int o = t;
    float mean = g_sum2[o]*(1.0f/MTOT);
    float var  = g_sq2[o]*(1.0f/MTOT) - mean*mean;
    float a    = gamma2[o]*rsqrtf(var + EPSF);
    float cc   = beta2[o] - mean*a;
    float v = (a>=0.f) ? fmaf(a, g_mx[(size_t)q*CC+o], cc)
                       : fmaf(a, g_mn[(size_t)q*CC+o], cc);
    out[(size_t)BB*SS*3 + (size_t)q*CC + o] = fmaxf(v, 0.f);
    if (t < 3){
        int cent = g_cent[q];
        out[(size_t)q*3 + t] = pos[(size_t)(b*NN + cent)*3 + t];
    }
}

// ---------------- launch ----------------
extern "C" void kernel_launch(void* const* d_in, const int* in_sizes, int n_in,
                              void* d_out, int out_size){
    const float* pos    = (const float*)d_in[0];
    const float* feat   = (const float*)d_in[1];
    const float* W1     = (const float*)d_in[2];
    const float* b1     = (const float*)d_in[3];
    const float* gamma1 = (const float*)d_in[4];
    const float* beta1  = (const float*)d_in[5];
    const float* W2     = (const float*)d_in[6];
    const float* b2     = (const float*)d_in[7];
    const float* gamma2 = (const float*)d_in[8];
    const float* beta2  = (const float*)d_in[9];
    float* out = (float*)d_out;

    const int mega1_smem = 288 + NN*3*4 + SS*4 + (NN/32)*4 + 64;          // ~54 KB
    const int gemm2_smem = (128 + 256) * ASTR * sizeof(float);            // 55296 B
    cudaFuncSetAttribute(k_mega1,  cudaFuncAttributeMaxDynamicSharedMemorySize, mega1_smem);
    cudaFuncSetAttribute(k_gemm2m, cudaFuncAttributeMaxDynamicSharedMemorySize, gemm2_smem);

    k_prep  <<<256, 256>>>(W1, W2);                               // 1
    k_mega1 <<<4 + (BB*NN)/16, 512, mega1_smem>>>(pos, feat);     // 2
    k_qgemm <<<(BB*SS)/16, 256>>>(feat);                          // 3
    k_knns  <<<BB*SS, 256>>>(pos, b1);                            // 4 -> profiled
    k_gemm2m<<<BB*SS/2, 256, gemm2_smem>>>(b1, gamma1, beta1, b2);// 5
    k_out   <<<BB*SS, 256>>>(pos, gamma2, beta2, out);            // 6
}

// round 13
// speedup vs baseline: 1.0344x; 1.0344x over previous
#include <cuda_runtime.h>
#include <cuda_bf16.h>
#include <math.h>
#include <stdint.h>

#define BB 4
#define NN 4096
#define FF 128
#define SS 1024
#define KK 64
#define CC 256
#define MTOT (BB*SS*KK)
#define EPSF 1e-5f

// ---------------- device scratch ----------------
__device__ int   g_cent[BB*SS];
__device__ int   g_group[BB*SS*KK];
__device__ float g_P[BB*NN*CC];
__device__ float g_Q[BB*SS*CC];
__device__ float g_W2rt[CC*CC];
__device__ float g_sum1[CC], g_sq1[CC], g_sum2[CC], g_sq2[CC];
__device__ float g_mx[BB*SS*CC], g_mn[BB*SS*CC];

__device__ __forceinline__ float to_tf32(float x){
    unsigned u;
    asm("cvt.rna.tf32.f32 %0, %1;" : "=r"(u) : "f"(x));
    return __uint_as_float(u);
}
// packed f32x2 helpers (per-component rounding == scalar FADD/FMUL/FFMA)
__device__ __forceinline__ unsigned long long pk2(float lo, float hi){
    unsigned long long r;
    asm("mov.b64 %0, {%1,%2};" : "=l"(r) : "f"(lo), "f"(hi));
    return r;
}
__device__ __forceinline__ void upk2(unsigned long long v, float& lo, float& hi){
    asm("mov.b64 {%0,%1}, %2;" : "=f"(lo), "=f"(hi) : "l"(v));
}
__device__ __forceinline__ unsigned long long add2(unsigned long long a, unsigned long long b){
    unsigned long long r; asm("add.rn.f32x2 %0,%1,%2;" : "=l"(r) : "l"(a), "l"(b)); return r;
}
__device__ __forceinline__ unsigned long long mul2(unsigned long long a, unsigned long long b){
    unsigned long long r; asm("mul.rn.f32x2 %0,%1,%2;" : "=l"(r) : "l"(a), "l"(b)); return r;
}
__device__ __forceinline__ unsigned long long fma2(unsigned long long a, unsigned long long b, unsigned long long c){
    unsigned long long r; asm("fma.rn.f32x2 %0,%1,%2,%3;" : "=l"(r) : "l"(a), "l"(b), "l"(c)); return r;
}

// ---------------- mega1 (256 thr): FPS [0..3] || pgemm [4..1027] || misc [1028] ----------------
extern __shared__ char mega_smem[];

__device__ void fps_body(const float* __restrict__ pos, int b){
    // layout: slots[2][8] u64 (128B) | s_pos | s_sel | s_mask
    unsigned long long* slots = (unsigned long long*)mega_smem;
    float*    s_pos  = (float*)(mega_smem + 128);
    int*      s_sel  = (int*)(mega_smem + 128 + NN*3*4);
    unsigned* s_mask = (unsigned*)(mega_smem + 128 + NN*3*4 + SS*4);
    volatile unsigned long long* vslots = (volatile unsigned long long*)slots;
    int t = threadIdx.x;
    const float* bp = pos + (size_t)b*NN*3;

    for (int i=t; i<NN*3; i+=256) s_pos[i] = bp[i];
    if (t < 16) slots[t] = 0ull;
    if (t==0) s_sel[0] = 0;
    __syncthreads();

    unsigned long long px2[8], py2[8], pz2[8];
    float dd[16];
    float qx=s_pos[0], qy=s_pos[1], qz=s_pos[2];
    float vmaxf = 0.f;
#pragma unroll
    for (int jp=0;jp<8;jp++){
        int i0 = t + 256*(2*jp), i1 = t + 256*(2*jp+1);
        float x0=s_pos[3*i0], y0=s_pos[3*i0+1], z0=s_pos[3*i0+2];
        float x1=s_pos[3*i1], y1=s_pos[3*i1+1], z1=s_pos[3*i1+2];
        px2[jp]=pk2(x0,x1); py2[jp]=pk2(y0,y1); pz2[jp]=pk2(z0,z1);
        float dx0=x0-qx, dy0=y0-qy, dz0=z0-qz;
        float dx1=x1-qx, dy1=y1-qy, dz1=z1-qz;
        dd[2*jp]   = dx0*dx0 + dy0*dy0 + dz0*dz0;
        dd[2*jp+1] = dx1*dx1 + dy1*dy1 + dz1*dz1;
        vmaxf = fmaxf(vmaxf, fmaxf(dd[2*jp], dd[2*jp+1]));
    }

    int wid = t >> 5, lane = t & 31;
#pragma unroll 1
    for (int it=1; it<SS; it++){
        unsigned tag = (unsigned)it & 0x3FFu;
        int par = it & 1;
        unsigned ub = __float_as_uint(vmaxf);            // dists >= 0: bits order-monotone
        unsigned rv = __reduce_max_sync(0xffffffffu, ub);
        unsigned cand = 0u;
        if (ub == rv){
            int idx = 0;
#pragma unroll
            for (int j=15;j>=0;j--)
                if (__float_as_uint(dd[j]) == rv) idx = t + 256*j;   // ends at smallest j
            cand = 0xFFFu & ~(unsigned)idx;
        }
        unsigned ri = __reduce_max_sync(0xffffffffu, cand);  // max ~idx == min idx
        if (lane==0)
            vslots[par*8 + wid] = ((unsigned long long)rv << 22)
                                | ((unsigned long long)ri << 10)
                                | (unsigned long long)tag;
        // EVERY warp: lanes 0-7 poll one slot each (parallel), 2x REDUX, shfl-broadcast
        unsigned mi = 0u;
        if (lane < 8){
            unsigned long long v;
            do { v = vslots[par*8 + lane]; } while ((unsigned)(v & 0x3FFull) != tag);
            unsigned val = (unsigned)(v >> 22);
            unsigned rid = (unsigned)((v >> 10) & 0xFFFull);
            unsigned mv = __reduce_max_sync(0xFFu, val);
            unsigned c2 = (val==mv) ? rid : 0u;
            mi = __reduce_max_sync(0xFFu, c2);
        }
        mi = __shfl_sync(0xffffffffu, mi, 0);
        int nxt = (int)(0xFFFu & ~mi);
        if (t==0) s_sel[it] = nxt;
        float cx=s_pos[3*nxt], cy=s_pos[3*nxt+1], cz=s_pos[3*nxt+2];
        unsigned long long ncx=pk2(-cx,-cx), ncy=pk2(-cy,-cy), ncz=pk2(-cz,-cz);
        float nv = 0.f;
#pragma unroll
        for (int jp=0;jp<8;jp++){
            unsigned long long dx2=add2(px2[jp],ncx);
            unsigned long long dy2=add2(py2[jp],ncy);
            unsigned long long dz2=add2(pz2[jp],ncz);
            unsigned long long d2 = mul2(dx2,dx2);
            d2 = fma2(dy2,dy2,d2);
            d2 = fma2(dz2,dz2,d2);
            float dlo,dhi; upk2(d2,dlo,dhi);
            float a = fminf(dd[2*jp],   dlo);
            float c = fminf(dd[2*jp+1], dhi);
            dd[2*jp]=a; dd[2*jp+1]=c;
            nv = fmaxf(nv, fmaxf(a,c));
        }
        vmaxf = nv;
    }
    __syncthreads();
    if (t < NN/32) s_mask[t]=0u;
    __syncthreads();
    for (int i=t; i<SS; i+=256) atomicOr(&s_mask[s_sel[i]>>5], 1u<<(s_sel[i]&31));
    __syncthreads();
    for (int i=t; i<SS; i+=256){
        int idx=s_sel[i];
        int w=idx>>5, r=0;
        for (int ww=0; ww<w; ww++) r += __popc(s_mask[ww]);
        r += __popc(s_mask[w] & ((1u<<(idx&31))-1u));
        g_cent[b*SS + r] = idx;
    }
}

// pgemm reads W1 directly (no prep): w_sum[c] = tf32(W1a[o][c]) + tf32(W1b[o][c])
__device__ void pgemm_body(const float* __restrict__ feat, const float* __restrict__ W1, int blk){
    float (*sf)[FF] = (float (*)[FF])mega_smem;
    int r0 = blk*16, t = threadIdx.x;
    for (int i=t; i<16*FF; i+=256)
        sf[i/FF][i%FF] = to_tf32(feat[(size_t)(r0 + i/FF)*FF + (i%FF)]);
    __syncthreads();
    int o = t;
    const float* wrow = W1 + (size_t)o*(2*FF);
    float acc[16];
#pragma unroll
    for (int r=0;r<16;r++) acc[r]=0.f;
    for (int c4=0; c4<FF; c4+=4){
        float4 wa = *(const float4*)(wrow + c4);
        float4 wb = *(const float4*)(wrow + FF + c4);
        float w0 = to_tf32(wa.x)+to_tf32(wb.x);
        float w1 = to_tf32(wa.y)+to_tf32(wb.y);
        float w2 = to_tf32(wa.z)+to_tf32(wb.z);
        float w3 = to_tf32(wa.w)+to_tf32(wb.w);
#pragma unroll
        for (int r=0;r<16;r++){
            acc[r]=fmaf(sf[r][c4+0], w0, acc[r]);
            acc[r]=fmaf(sf[r][c4+1], w1, acc[r]);
            acc[r]=fmaf(sf[r][c4+2], w2, acc[r]);
            acc[r]=fmaf(sf[r][c4+3], w3, acc[r]);
        }
    }
#pragma unroll
    for (int r=0;r<16;r++) g_P[(size_t)(r0+r)*CC + o] = acc[r];
}

// misc block: W2rt + zero stats
__device__ void misc_body(const float* __restrict__ W2){
    int t = threadIdx.x;
    for (int i=t*4; i<CC*CC; i+=256*4){
        float4 w = *(const float4*)(W2 + i);
        float4 v; v.x=to_tf32(w.x); v.y=to_tf32(w.y); v.z=to_tf32(w.z); v.w=to_tf32(w.w);
        *(float4*)(g_W2rt + i) = v;
    }
    if (t < CC){
        g_sum1[t]=0.f; g_sq1[t]=0.f; g_sum2[t]=0.f; g_sq2[t]=0.f;
    }
}

__global__ __launch_bounds__(256) void k_mega1(const float* __restrict__ pos,
                                               const float* __restrict__ feat,
                                               const float* __restrict__ W1,
                                               const float* __restrict__ W2){
    if (blockIdx.x < 4)          fps_body(pos, blockIdx.x);
    else if (blockIdx.x < 1028)  pgemm_body(feat, W1, blockIdx.x - 4);
    else                         misc_body(W2);
}

// ---------------- Q = tf32(centroid feat) @ tf32(W1a)^T (reads W1 directly) ----------------
__global__ __launch_bounds__(256) void k_qgemm(const float* __restrict__ feat,
                                               const float* __restrict__ W1){
    __shared__ float sf[16][FF];
    int r0 = blockIdx.x*16, t = threadIdx.x;
    for (int i=t; i<16*FF; i+=256){
        int rr = r0 + i/FF;
        int b  = rr / SS;
        int cent = g_cent[rr];
        sf[i/FF][i%FF] = to_tf32(feat[(size_t)(b*NN + cent)*FF + (i%FF)]);
    }
    __syncthreads();
    int o = t;
    const float* wrow = W1 + (size_t)o*(2*FF);
    float acc[16];
#pragma unroll
    for (int r=0;r<16;r++) acc[r]=0.f;
    for (int c4=0; c4<FF; c4+=4){
        float4 wa = *(const float4*)(wrow + c4);
        float w0 = to_tf32(wa.x), w1 = to_tf32(wa.y), w2 = to_tf32(wa.z), w3 = to_tf32(wa.w);
#pragma unroll
        for (int r=0;r<16;r++){
            acc[r]=fmaf(sf[r][c4+0], w0, acc[r]);
            acc[r]=fmaf(sf[r][c4+1], w1, acc[r]);
            acc[r]=fmaf(sf[r][c4+2], w2, acc[r]);
            acc[r]=fmaf(sf[r][c4+3], w3, acc[r]);
        }
    }
#pragma unroll
    for (int r=0;r<16;r++) g_Q[(size_t)(r0+r)*CC + o] = acc[r];
}

// ---------------- KNN (256 thr) + fused BN1 stats ----------------
__global__ __launch_bounds__(256) void k_knns(const float* __restrict__ pos,
                                              const float* __restrict__ b1){
    __shared__ unsigned sbits[NN];
    __shared__ int shist[256];
    __shared__ unsigned s_prefix;
    __shared__ int s_want, s_cnt, s_eqcnt;
    __shared__ int s_eq[256];
    __shared__ int s_g[KK];
    int q = blockIdx.x, t = threadIdx.x;
    int b = q / SS;
    int c = g_cent[q];
    const float* bp = pos + (size_t)b*NN*3;
    float qx=bp[3*c], qy=bp[3*c+1], qz=bp[3*c+2];
    float qq = __fadd_rn(__fadd_rn(__fmul_rn(qx,qx), __fmul_rn(qy,qy)), __fmul_rn(qz,qz));

    for (int i=t; i<NN; i+=256){
        float x=bp[3*i], y=bp[3*i+1], z=bp[3*i+2];
        float pp = __fadd_rn(__fadd_rn(__fmul_rn(x,x), __fmul_rn(y,y)), __fmul_rn(z,z));
        float dot = __fadd_rn(__fadd_rn(__fmul_rn(qx,x), __fmul_rn(qy,y)), __fmul_rn(qz,z));
        float d = __fadd_rn(__fadd_rn(__fmul_rn(-2.0f, dot), qq), pp);
        unsigned u = __float_as_uint(d);
        u = (u & 0x80000000u) ? ~u : (u | 0x80000000u);
        sbits[i] = u;
    }
    if (t==0){ s_prefix=0u; s_want=KK; s_cnt=0; s_eqcnt=0; }
    __syncthreads();

    for (int pass=0; pass<4; pass++){
        int shift = 24 - 8*pass;
        shist[t]=0;
        __syncthreads();
        unsigned pref = s_prefix;
        for (int i=t; i<NN; i+=256){
            unsigned u = sbits[i];
            bool m = (pass==0) || ((u >> (shift+8)) == pref);
            if (m) atomicAdd(&shist[(u>>shift)&0xFFu], 1);
        }
        __syncthreads();
        if (t==0){
            int want=s_want, cum=0, bin;
            for (bin=0; bin<256; bin++){
                int h=shist[bin];
                if (cum+h >= want) break;
                cum += h;
            }
            s_want = want - cum;
            s_prefix = (s_prefix<<8) | (unsigned)bin;
        }
        __syncthreads();
    }
    unsigned T = s_prefix;
    for (int i=t; i<NN; i+=256){
        unsigned u = sbits[i];
        if (u < T){
            int p = atomicAdd(&s_cnt,1);
            g_group[q*KK + p] = i;
            s_g[p] = i;
        } else if (u == T){
            int p = atomicAdd(&s_eqcnt,1);
            if (p < 256) s_eq[p] = i;
        }
    }
    __syncthreads();
    if (t==0){
        int base = s_cnt;
        int nd   = KK - base;
        int ec   = s_eqcnt;
        if (ec <= 256){
            for (int r=0; r<nd; r++){
                int mi=r;
                for (int j=r+1; j<ec; j++) if (s_eq[j] < s_eq[mi]) mi=j;
                int tmp=s_eq[r]; s_eq[r]=s_eq[mi]; s_eq[mi]=tmp;
                g_group[q*KK + base + r] = s_eq[r];
                s_g[base + r] = s_eq[r];
            }
        } else {
            int w=nd, p=base;
            for (int i=0; i<NN && w>0; i++)
                if (sbits[i]==T){ g_group[q*KK + p] = i; s_g[p] = i; p++; w--; }
        }
    }
    __syncthreads();
    // fused BN1 stats: 256 threads, one channel each
    int o = t;
    float base = b1[o] - g_Q[(size_t)q*CC + o];
    float sum=0.f, sq=0.f;
    const float* Pb = g_P + (size_t)b*NN*CC;
#pragma unroll 4
    for (int k=0;k<KK;k++){
        float h = Pb[(size_t)s_g[k]*CC + o] + base;
        sum += h; sq = fmaf(h,h,sq);
    }
    atomicAdd(&g_sum1[o], sum);
    atomicAdd(&g_sq1[o],  sq);
}

// ---------------- layer2 GEMM via mma.sync tf32 (R7 config) ----------------
#define ASTR 36
extern __shared__ float dyn_smem[];
__global__ __launch_bounds__(256, 1) void k_gemm2m(const float* __restrict__ b1,
                                                   const float* __restrict__ gamma1,
                                                   const float* __restrict__ beta1,
                                                   const float* __restrict__ b2){
    __shared__ float a_s[CC];
    __shared__ float d_s[2*CC];
    __shared__ int   s_nbr[128];

    float* As = dyn_smem;             // [128][ASTR]
    float* Bs = dyn_smem + 128*ASTR;  // [256][ASTR]

    int t = threadIdx.x;
    int bid = blockIdx.x;
    int q0 = 2*bid;
    int batch = q0 >> 10;

    if (t < 128) s_nbr[t] = g_group[bid*128 + t];
    {
        int c = t;
        float mean = g_sum1[c]*(1.0f/MTOT);
        float var  = g_sq1[c]*(1.0f/MTOT) - mean*mean;
        float a    = gamma1[c]*rsqrtf(var + EPSF);
        float ccv  = beta1[c] - mean*a;
        a_s[c] = a;
        d_s[c]    = fmaf(a, b1[c] - g_Q[(size_t)q0*CC + c], ccv);
        d_s[CC+c] = fmaf(a, b1[c] - g_Q[(size_t)(q0+1)*CC + c], ccv);
    }

    int lane = t & 31, wid = t >> 5;
    int warpM = wid >> 2, warpN = wid & 3;
    int r0 = warpM*64, n0 = warpN*64;
    int g = lane >> 2, tig = lane & 3;

    float acc[4][8][4];
#pragma unroll
    for (int mt=0;mt<4;mt++)
#pragma unroll
        for (int nt=0;nt<8;nt++)
#pragma unroll
            for (int i=0;i<4;i++) acc[mt][nt][i]=0.f;

    const uint32_t* Ab = (const uint32_t*)As + (r0+g)*ASTR + tig;
    const uint32_t* Bb = (const uint32_t*)Bs + (n0+g)*ASTR + tig;

    int am = t >> 1;
    int aj0 = (t & 1) * 16;
    int agrp = am >> 6;
    __syncthreads();
    int nbr = s_nbr[am];
    const float* Pr = g_P + ((size_t)(batch*NN + nbr))*CC;

#pragma unroll 1
    for (int kc=0; kc<8; kc++){
        if (kc > 0) __syncthreads();
        {
            const float* dv = d_s + agrp*CC + kc*32 + aj0;
            const float* av = a_s + kc*32 + aj0;
            const float* pr = Pr + kc*32 + aj0;
            float* arow = As + am*ASTR + aj0;
#pragma unroll
            for (int i=0;i<4;i++){
                float4 p = *(const float4*)(pr + 4*i);
                float4 v;
                v.x = to_tf32(fmaxf(fmaf(av[4*i+0], p.x, dv[4*i+0]), 0.f));
                v.y = to_tf32(fmaxf(fmaf(av[4*i+1], p.y, dv[4*i+1]), 0.f));
                v.z = to_tf32(fmaxf(fmaf(av[4*i+2], p.z, dv[4*i+2]), 0.f));
                v.w = to_tf32(fmaxf(fmaf(av[4*i+3], p.w, dv[4*i+3]), 0.f));
                *(float4*)(arow + 4*i) = v;
            }
        }
        {
            const float* wr = g_W2rt + (size_t)t*CC + kc*32;
            float* brow = Bs + t*ASTR;
#pragma unroll
            for (int i=0;i<8;i++)
                *(float4*)(brow + 4*i) = *(const float4*)(wr + 4*i);
        }
        __syncthreads();
#pragma unroll
        for (int kk=0; kk<4; kk++){
            int kb = kk*8;
            uint32_t af[4][4];
#pragma unroll
            for (int mt=0;mt<4;mt++){
                af[mt][0] = Ab[(mt*16    )*ASTR + kb];
                af[mt][1] = Ab[(mt*16 + 8)*ASTR + kb];
                af[mt][2] = Ab[(mt*16    )*ASTR + kb + 4];
                af[mt][3] = Ab[(mt*16 + 8)*ASTR + kb + 4];
            }
            uint32_t bf[8][2];
#pragma unroll
            for (int nt=0;nt<8;nt++){
                bf[nt][0] = Bb[(nt*8)*ASTR + kb];
                bf[nt][1] = Bb[(nt*8)*ASTR + kb + 4];
            }
#pragma unroll
            for (int mt=0;mt<4;mt++){
#pragma unroll
                for (int nt=0;nt<8;nt++){
                    asm volatile(
                        "mma.sync.aligned.m16n8k8.row.col.f32.tf32.tf32.f32 "
                        "{%0,%1,%2,%3}, {%4,%5,%6,%7}, {%8,%9}, {%0,%1,%2,%3};"
                        : "+f"(acc[mt][nt][0]), "+f"(acc[mt][nt][1]),
                          "+f"(acc[mt][nt][2]), "+f"(acc[mt][nt][3])
                        : "r"(af[mt][0]), "r"(af[mt][1]), "r"(af[mt][2]), "r"(af[mt][3]),
                          "r"(bf[nt][0]), "r"(bf[nt][1]));
                }
            }
        }
    }

    int q = q0 + warpM;
#pragma unroll
    for (int nt=0; nt<8; nt++){
#pragma unroll
        for (int hc=0; hc<2; hc++){
            int col = n0 + nt*8 + 2*tig + hc;
            float bias = __ldg(&b2[col]);
            float mx=-3.402823466e38f, mn=3.402823466e38f, sum=0.f, sq=0.f;
#pragma unroll
            for (int mt=0;mt<4;mt++){
                float h0 = acc[mt][nt][hc]   + bias;
                float h1 = acc[mt][nt][2+hc] + bias;
                mx=fmaxf(mx,fmaxf(h0,h1)); mn=fminf(mn,fminf(h0,h1));
                sum += h0 + h1; sq = fmaf(h0,h0,sq); sq = fmaf(h1,h1,sq);
            }
#pragma unroll
            for (int off=4; off<=16; off<<=1){
                mx  = fmaxf(mx,  __shfl_xor_sync(0xffffffffu, mx,  off));
                mn  = fminf(mn,  __shfl_xor_sync(0xffffffffu, mn,  off));
                sum = sum +      __shfl_xor_sync(0xffffffffu, sum, off);
                sq  = sq +       __shfl_xor_sync(0xffffffffu, sq,  off);
            }
            if (g == 0){
                g_mx[(size_t)q*CC + col] = mx;
                g_mn[(size_t)q*CC + col] = mn;
                atomicAdd(&g_sum2[col], sum);
                atomicAdd(&g_sq2[col],  sq);
            }
        }
    }
}

// ---------------- BN2 + ReLU + maxpool + outputs ----------------
__global__ __launch_bounds__(256) void k_out(const float* __restrict__ pos,
                                             const float* __restrict__ gamma2,
                                             const float* __restrict__ beta2,
                                             float* __restrict__ out){
    int q = blockIdx.x, t = threadIdx.x, b = q/SS;
    int o = t;
    float mean = g_sum2[o]*(1.0f/MTOT);
    float var  = g_sq2[o]*(1.0f/MTOT) - mean*mean;
    float a    = gamma2[o]*rsqrtf(var + EPSF);
    float cc   = beta2[o] - mean*a;
    float v = (a>=0.f) ? fmaf(a, g_mx[(size_t)q*CC+o], cc)
                       : fmaf(a, g_mn[(size_t)q*CC+o], cc);
    out[(size_t)BB*SS*3 + (size_t)q*CC + o] = fmaxf(v, 0.f);
    if (t < 3){
        int cent = g_cent[q];
        out[(size_t)q*3 + t] = pos[(size_t)(b*NN + cent)*3 + t];
    }
}

// ---------------- launch ----------------
extern "C" void kernel_launch(void* const* d_in, const int* in_sizes, int n_in,
                              void* d_out, int out_size){
    const float* pos    = (const float*)d_in[0];
    const float* feat   = (const float*)d_in[1];
    const float* W1     = (const float*)d_in[2];
    const float* b1     = (const float*)d_in[3];
    const float* gamma1 = (const float*)d_in[4];
    const float* beta1  = (const float*)d_in[5];
    const float* W2     = (const float*)d_in[6];
    const float* b2     = (const float*)d_in[7];
    const float* gamma2 = (const float*)d_in[8];
    const float* beta2  = (const float*)d_in[9];
    float* out = (float*)d_out;

    const int mega1_smem = 128 + NN*3*4 + SS*4 + (NN/32)*4 + 64;          // ~54 KB
    const int gemm2_smem = (128 + 256) * ASTR * sizeof(float);            // 55296 B
    cudaFuncSetAttribute(k_mega1,  cudaFuncAttributeMaxDynamicSharedMemorySize, mega1_smem);
    cudaFuncSetAttribute(k_gemm2m, cudaFuncAttributeMaxDynamicSharedMemorySize, gemm2_smem);

    k_mega1 <<<4 + (BB*NN)/16 + 1, 256, mega1_smem>>>(pos, feat, W1, W2); // 1
    k_qgemm <<<(BB*SS)/16, 256>>>(feat, W1);                              // 2
    k_knns  <<<BB*SS, 256>>>(pos, b1);                                    // 3
    k_gemm2m<<<BB*SS/2, 256, gemm2_smem>>>(b1, gamma1, beta1, b2);        // 4 -> profiled
    k_out   <<<BB*SS, 256>>>(pos, gamma2, beta2, out);                    // 5
}

// round 14
// speedup vs baseline: 1.0959x; 1.0595x over previous
#include <cuda_runtime.h>
#include <cuda_bf16.h>
#include <math.h>
#include <stdint.h>

#define BB 4
#define NN 4096
#define FF 128
#define SS 1024
#define KK 64
#define CC 256
#define MTOT (BB*SS*KK)
#define EPSF 1e-5f

// ---------------- device scratch ----------------
__device__ int   g_cent[BB*SS];
__device__ int   g_group[BB*SS*KK];
__device__ float g_P[BB*NN*CC];
__device__ float g_Q[BB*SS*CC];
__device__ float g_W2rt[CC*CC];
__device__ float g_sum1[CC], g_sq1[CC], g_sum2[CC], g_sq2[CC];
__device__ float g_mx[BB*SS*CC], g_mn[BB*SS*CC];

__device__ __forceinline__ float to_tf32(float x){
    unsigned u;
    asm("cvt.rna.tf32.f32 %0, %1;" : "=r"(u) : "f"(x));
    return __uint_as_float(u);
}
// packed f32x2 helpers (per-component rounding == scalar FADD/FMUL/FFMA)
__device__ __forceinline__ unsigned long long pk2(float lo, float hi){
    unsigned long long r;
    asm("mov.b64 %0, {%1,%2};" : "=l"(r) : "f"(lo), "f"(hi));
    return r;
}
__device__ __forceinline__ void upk2(unsigned long long v, float& lo, float& hi){
    asm("mov.b64 {%0,%1}, %2;" : "=f"(lo), "=f"(hi) : "l"(v));
}
__device__ __forceinline__ unsigned long long add2(unsigned long long a, unsigned long long b){
    unsigned long long r; asm("add.rn.f32x2 %0,%1,%2;" : "=l"(r) : "l"(a), "l"(b)); return r;
}
__device__ __forceinline__ unsigned long long mul2(unsigned long long a, unsigned long long b){
    unsigned long long r; asm("mul.rn.f32x2 %0,%1,%2;" : "=l"(r) : "l"(a), "l"(b)); return r;
}
__device__ __forceinline__ unsigned long long fma2(unsigned long long a, unsigned long long b, unsigned long long c){
    unsigned long long r; asm("fma.rn.f32x2 %0,%1,%2,%3;" : "=l"(r) : "l"(a), "l"(b), "l"(c)); return r;
}

// ---------------- mega1 (256 thr): FPS [0..3] || pgemm [4..1027] || misc [1028] ----------------
extern __shared__ char mega_smem[];

__device__ void fps_body(const float* __restrict__ pos, int b){
    unsigned long long* slots = (unsigned long long*)mega_smem;
    float*    s_pos  = (float*)(mega_smem + 128);
    int*      s_sel  = (int*)(mega_smem + 128 + NN*3*4);
    unsigned* s_mask = (unsigned*)(mega_smem + 128 + NN*3*4 + SS*4);
    volatile unsigned long long* vslots = (volatile unsigned long long*)slots;
    int t = threadIdx.x;
    const float* bp = pos + (size_t)b*NN*3;

    for (int i=t; i<NN*3; i+=256) s_pos[i] = bp[i];
    if (t < 16) slots[t] = 0ull;
    if (t==0) s_sel[0] = 0;
    __syncthreads();

    unsigned long long px2[8], py2[8], pz2[8];
    float dd[16];
    float qx=s_pos[0], qy=s_pos[1], qz=s_pos[2];
    float vmaxf = 0.f;
#pragma unroll
    for (int jp=0;jp<8;jp++){
        int i0 = t + 256*(2*jp), i1 = t + 256*(2*jp+1);
        float x0=s_pos[3*i0], y0=s_pos[3*i0+1], z0=s_pos[3*i0+2];
        float x1=s_pos[3*i1], y1=s_pos[3*i1+1], z1=s_pos[3*i1+2];
        px2[jp]=pk2(x0,x1); py2[jp]=pk2(y0,y1); pz2[jp]=pk2(z0,z1);
        float dx0=x0-qx, dy0=y0-qy, dz0=z0-qz;
        float dx1=x1-qx, dy1=y1-qy, dz1=z1-qz;
        dd[2*jp]   = dx0*dx0 + dy0*dy0 + dz0*dz0;
        dd[2*jp+1] = dx1*dx1 + dy1*dy1 + dz1*dz1;
        vmaxf = fmaxf(vmaxf, fmaxf(dd[2*jp], dd[2*jp+1]));
    }

    int wid = t >> 5, lane = t & 31;
#pragma unroll 1
    for (int it=1; it<SS; it++){
        unsigned tag = (unsigned)it & 0x3FFu;
        int par = it & 1;
        unsigned ub = __float_as_uint(vmaxf);
        unsigned rv = __reduce_max_sync(0xffffffffu, ub);
        unsigned cand = 0u;
        if (ub == rv){
            int idx = 0;
#pragma unroll
            for (int j=15;j>=0;j--)
                if (__float_as_uint(dd[j]) == rv) idx = t + 256*j;
            cand = 0xFFFu & ~(unsigned)idx;
        }
        unsigned ri = __reduce_max_sync(0xffffffffu, cand);
        if (lane==0)
            vslots[par*8 + wid] = ((unsigned long long)rv << 22)
                                | ((unsigned long long)ri << 10)
                                | (unsigned long long)tag;
        unsigned mi = 0u;
        if (lane < 8){
            unsigned long long v;
            do { v = vslots[par*8 + lane]; } while ((unsigned)(v & 0x3FFull) != tag);
            unsigned val = (unsigned)(v >> 22);
            unsigned rid = (unsigned)((v >> 10) & 0xFFFull);
            unsigned mv = __reduce_max_sync(0xFFu, val);
            unsigned c2 = (val==mv) ? rid : 0u;
            mi = __reduce_max_sync(0xFFu, c2);
        }
        mi = __shfl_sync(0xffffffffu, mi, 0);
        int nxt = (int)(0xFFFu & ~mi);
        if (t==0) s_sel[it] = nxt;
        float cx=s_pos[3*nxt], cy=s_pos[3*nxt+1], cz=s_pos[3*nxt+2];
        unsigned long long ncx=pk2(-cx,-cx), ncy=pk2(-cy,-cy), ncz=pk2(-cz,-cz);
        float nv = 0.f;
#pragma unroll
        for (int jp=0;jp<8;jp++){
            unsigned long long dx2=add2(px2[jp],ncx);
            unsigned long long dy2=add2(py2[jp],ncy);
            unsigned long long dz2=add2(pz2[jp],ncz);
            unsigned long long d2 = mul2(dx2,dx2);
            d2 = fma2(dy2,dy2,d2);
            d2 = fma2(dz2,dz2,d2);
            float dlo,dhi; upk2(d2,dlo,dhi);
            float a = fminf(dd[2*jp],   dlo);
            float c = fminf(dd[2*jp+1], dhi);
            dd[2*jp]=a; dd[2*jp+1]=c;
            nv = fmaxf(nv, fmaxf(a,c));
        }
        vmaxf = nv;
    }
    __syncthreads();
    if (t < NN/32) s_mask[t]=0u;
    __syncthreads();
    for (int i=t; i<SS; i+=256) atomicOr(&s_mask[s_sel[i]>>5], 1u<<(s_sel[i]&31));
    __syncthreads();
    for (int i=t; i<SS; i+=256){
        int idx=s_sel[i];
        int w=idx>>5, r=0;
        for (int ww=0; ww<w; ww++) r += __popc(s_mask[ww]);
        r += __popc(s_mask[w] & ((1u<<(idx&31))-1u));
        g_cent[b*SS + r] = idx;
    }
}

__device__ void pgemm_body(const float* __restrict__ feat, const float* __restrict__ W1, int blk){
    float (*sf)[FF] = (float (*)[FF])mega_smem;
    int r0 = blk*16, t = threadIdx.x;
    for (int i=t; i<16*FF; i+=256)
        sf[i/FF][i%FF] = to_tf32(feat[(size_t)(r0 + i/FF)*FF + (i%FF)]);
    __syncthreads();
    int o = t;
    const float* wrow = W1 + (size_t)o*(2*FF);
    float acc[16];
#pragma unroll
    for (int r=0;r<16;r++) acc[r]=0.f;
    for (int c4=0; c4<FF; c4+=4){
        float4 wa = *(const float4*)(wrow + c4);
        float4 wb = *(const float4*)(wrow + FF + c4);
        float w0 = to_tf32(wa.x)+to_tf32(wb.x);
        float w1 = to_tf32(wa.y)+to_tf32(wb.y);
        float w2 = to_tf32(wa.z)+to_tf32(wb.z);
        float w3 = to_tf32(wa.w)+to_tf32(wb.w);
#pragma unroll
        for (int r=0;r<16;r++){
            acc[r]=fmaf(sf[r][c4+0], w0, acc[r]);
            acc[r]=fmaf(sf[r][c4+1], w1, acc[r]);
            acc[r]=fmaf(sf[r][c4+2], w2, acc[r]);
            acc[r]=fmaf(sf[r][c4+3], w3, acc[r]);
        }
    }
#pragma unroll
    for (int r=0;r<16;r++) g_P[(size_t)(r0+r)*CC + o] = acc[r];
}

__device__ void misc_body(const float* __restrict__ W2){
    int t = threadIdx.x;
    for (int i=t*4; i<CC*CC; i+=256*4){
        float4 w = *(const float4*)(W2 + i);
        float4 v; v.x=to_tf32(w.x); v.y=to_tf32(w.y); v.z=to_tf32(w.z); v.w=to_tf32(w.w);
        *(float4*)(g_W2rt + i) = v;
    }
    if (t < CC){
        g_sum1[t]=0.f; g_sq1[t]=0.f; g_sum2[t]=0.f; g_sq2[t]=0.f;
    }
}

__global__ __launch_bounds__(256) void k_mega1(const float* __restrict__ pos,
                                               const float* __restrict__ feat,
                                               const float* __restrict__ W1,
                                               const float* __restrict__ W2){
    if (blockIdx.x < 4)          fps_body(pos, blockIdx.x);
    else if (blockIdx.x < 1028)  pgemm_body(feat, W1, blockIdx.x - 4);
    else                         misc_body(W2);
}

// ---------------- Q = tf32(centroid feat) @ tf32(W1a)^T ----------------
__global__ __launch_bounds__(256) void k_qgemm(const float* __restrict__ feat,
                                               const float* __restrict__ W1){
    __shared__ float sf[16][FF];
    int r0 = blockIdx.x*16, t = threadIdx.x;
    for (int i=t; i<16*FF; i+=256){
        int rr = r0 + i/FF;
        int b  = rr / SS;
        int cent = g_cent[rr];
        sf[i/FF][i%FF] = to_tf32(feat[(size_t)(b*NN + cent)*FF + (i%FF)]);
    }
    __syncthreads();
    int o = t;
    const float* wrow = W1 + (size_t)o*(2*FF);
    float acc[16];
#pragma unroll
    for (int r=0;r<16;r++) acc[r]=0.f;
    for (int c4=0; c4<FF; c4+=4){
        float4 wa = *(const float4*)(wrow + c4);
        float w0 = to_tf32(wa.x), w1 = to_tf32(wa.y), w2 = to_tf32(wa.z), w3 = to_tf32(wa.w);
#pragma unroll
        for (int r=0;r<16;r++){
            acc[r]=fmaf(sf[r][c4+0], w0, acc[r]);
            acc[r]=fmaf(sf[r][c4+1], w1, acc[r]);
            acc[r]=fmaf(sf[r][c4+2], w2, acc[r]);
            acc[r]=fmaf(sf[r][c4+3], w3, acc[r]);
        }
    }
#pragma unroll
    for (int r=0;r<16;r++) g_Q[(size_t)(r0+r)*CC + o] = acc[r];
}

// ---------------- KNN (256 thr) + fused BN1 stats ----------------
__global__ __launch_bounds__(256) void k_knns(const float* __restrict__ pos,
                                              const float* __restrict__ b1){
    __shared__ unsigned sbits[NN];
    __shared__ int shist[256];
    __shared__ unsigned s_prefix;
    __shared__ int s_want, s_cnt, s_eqcnt;
    __shared__ int s_eq[256];
    __shared__ int s_g[KK];
    int q = blockIdx.x, t = threadIdx.x;
    int b = q / SS;
    int c = g_cent[q];
    const float* bp = pos + (size_t)b*NN*3;
    float qx=bp[3*c], qy=bp[3*c+1], qz=bp[3*c+2];
    float qq = __fadd_rn(__fadd_rn(__fmul_rn(qx,qx), __fmul_rn(qy,qy)), __fmul_rn(qz,qz));

    for (int i=t; i<NN; i+=256){
        float x=bp[3*i], y=bp[3*i+1], z=bp[3*i+2];
        float pp = __fadd_rn(__fadd_rn(__fmul_rn(x,x), __fmul_rn(y,y)), __fmul_rn(z,z));
        float dot = __fadd_rn(__fadd_rn(__fmul_rn(qx,x), __fmul_rn(qy,y)), __fmul_rn(qz,z));
        float d = __fadd_rn(__fadd_rn(__fmul_rn(-2.0f, dot), qq), pp);
        unsigned u = __float_as_uint(d);
        u = (u & 0x80000000u) ? ~u : (u | 0x80000000u);
        sbits[i] = u;
    }
    if (t==0){ s_prefix=0u; s_want=KK; s_cnt=0; s_eqcnt=0; }
    __syncthreads();

    for (int pass=0; pass<4; pass++){
        int shift = 24 - 8*pass;
        shist[t]=0;
        __syncthreads();
        unsigned pref = s_prefix;
        for (int i=t; i<NN; i+=256){
            unsigned u = sbits[i];
            bool m = (pass==0) || ((u >> (shift+8)) == pref);
            if (m) atomicAdd(&shist[(u>>shift)&0xFFu], 1);
        }
        __syncthreads();
        if (t==0){
            int want=s_want, cum=0, bin;
            for (bin=0; bin<256; bin++){
                int h=shist[bin];
                if (cum+h >= want) break;
                cum += h;
            }
            s_want = want - cum;
            s_prefix = (s_prefix<<8) | (unsigned)bin;
        }
        __syncthreads();
    }
    unsigned T = s_prefix;
    for (int i=t; i<NN; i+=256){
        unsigned u = sbits[i];
        if (u < T){
            int p = atomicAdd(&s_cnt,1);
            g_group[q*KK + p] = i;
            s_g[p] = i;
        } else if (u == T){
            int p = atomicAdd(&s_eqcnt,1);
            if (p < 256) s_eq[p] = i;
        }
    }
    __syncthreads();
    if (t==0){
        int base = s_cnt;
        int nd   = KK - base;
        int ec   = s_eqcnt;
        if (ec <= 256){
            for (int r=0; r<nd; r++){
                int mi=r;
                for (int j=r+1; j<ec; j++) if (s_eq[j] < s_eq[mi]) mi=j;
                int tmp=s_eq[r]; s_eq[r]=s_eq[mi]; s_eq[mi]=tmp;
                g_group[q*KK + base + r] = s_eq[r];
                s_g[base + r] = s_eq[r];
            }
        } else {
            int w=nd, p=base;
            for (int i=0; i<NN && w>0; i++)
                if (sbits[i]==T){ g_group[q*KK + p] = i; s_g[p] = i; p++; w--; }
        }
    }
    __syncthreads();
    int o = t;
    float base = b1[o] - g_Q[(size_t)q*CC + o];
    float sum=0.f, sq=0.f;
    const float* Pb = g_P + (size_t)b*NN*CC;
#pragma unroll 4
    for (int k=0;k<KK;k++){
        float h = Pb[(size_t)s_g[k]*CC + o] + base;
        sum += h; sq = fmaf(h,h,sq);
    }
    atomicAdd(&g_sum1[o], sum);
    atomicAdd(&g_sq1[o],  sq);
}

// ---------------- layer2 GEMM via mma.sync tf32: M=128 x N=128 tile, 2 CTAs/SM ----------------
#define ASTR 36
extern __shared__ float dyn_smem[];
__global__ __launch_bounds__(256, 2) void k_gemm2m(const float* __restrict__ b1,
                                                   const float* __restrict__ gamma1,
                                                   const float* __restrict__ beta1,
                                                   const float* __restrict__ b2){
    __shared__ float a_s[CC];
    __shared__ float d_s[2*CC];
    __shared__ int   s_nbr[128];

    float* As = dyn_smem;             // [128][ASTR]
    float* Bs = dyn_smem + 128*ASTR;  // [128][ASTR]

    int t = threadIdx.x;
    int bid = blockIdx.x;
    int pair = bid >> 1;              // group-pair index (0..2047)
    int nh   = bid & 1;               // N half: 0 or 1
    int q0 = 2*pair;
    int batch = q0 >> 10;

    if (t < 128) s_nbr[t] = g_group[pair*128 + t];
    {
        int c = t;
        float mean = g_sum1[c]*(1.0f/MTOT);
        float var  = g_sq1[c]*(1.0f/MTOT) - mean*mean;
        float a    = gamma1[c]*rsqrtf(var + EPSF);
        float ccv  = beta1[c] - mean*a;
        a_s[c] = a;
        d_s[c]    = fmaf(a, b1[c] - g_Q[(size_t)q0*CC + c], ccv);
        d_s[CC+c] = fmaf(a, b1[c] - g_Q[(size_t)(q0+1)*CC + c], ccv);
    }

    int lane = t & 31, wid = t >> 5;
    int warpM = wid >> 2, warpN = wid & 3;
    int r0 = warpM*64, n0l = warpN*32;
    int g = lane >> 2, tig = lane & 3;

    float acc[4][4][4];
#pragma unroll
    for (int mt=0;mt<4;mt++)
#pragma unroll
        for (int nt=0;nt<4;nt++)
#pragma unroll
            for (int i=0;i<4;i++) acc[mt][nt][i]=0.f;

    const uint32_t* Ab = (const uint32_t*)As + (r0+g)*ASTR + tig;
    const uint32_t* Bb = (const uint32_t*)Bs + (n0l+g)*ASTR + tig;

    int am = t >> 1;
    int aj0 = (t & 1) * 16;
    int agrp = am >> 6;
    __syncthreads();
    int nbr = s_nbr[am];
    const float* Pr = g_P + ((size_t)(batch*NN + nbr))*CC;
    // B: row (t>>1) of this N-half, half (t&1)
    const float* Wr = g_W2rt + (size_t)(nh*128 + (t>>1))*CC;

#pragma unroll 1
    for (int kc=0; kc<8; kc++){
        if (kc > 0) __syncthreads();
        {   // A build: gather + BN1 + ReLU + tf32
            const float* dv = d_s + agrp*CC + kc*32 + aj0;
            const float* av = a_s + kc*32 + aj0;
            const float* pr = Pr + kc*32 + aj0;
            float* arow = As + am*ASTR + aj0;
#pragma unroll
            for (int i=0;i<4;i++){
                float4 p = *(const float4*)(pr + 4*i);
                float4 v;
                v.x = to_tf32(fmaxf(fmaf(av[4*i+0], p.x, dv[4*i+0]), 0.f));
                v.y = to_tf32(fmaxf(fmaf(av[4*i+1], p.y, dv[4*i+1]), 0.f));
                v.z = to_tf32(fmaxf(fmaf(av[4*i+2], p.z, dv[4*i+2]), 0.f));
                v.w = to_tf32(fmaxf(fmaf(av[4*i+3], p.w, dv[4*i+3]), 0.f));
                *(float4*)(arow + 4*i) = v;
            }
        }
        {   // B build: 128 rows x 32 floats, 2 threads per row
            const float* wr = Wr + kc*32 + aj0;
            float* brow = Bs + am*ASTR + aj0;
#pragma unroll
            for (int i=0;i<4;i++)
                *(float4*)(brow + 4*i) = *(const float4*)(wr + 4*i);
        }
        __syncthreads();
#pragma unroll
        for (int kk=0; kk<4; kk++){
            int kb = kk*8;
            uint32_t af[4][4];
#pragma unroll
            for (int mt=0;mt<4;mt++){
                af[mt][0] = Ab[(mt*16    )*ASTR + kb];
                af[mt][1] = Ab[(mt*16 + 8)*ASTR + kb];
                af[mt][2] = Ab[(mt*16    )*ASTR + kb + 4];
                af[mt][3] = Ab[(mt*16 + 8)*ASTR + kb + 4];
            }
            uint32_t bf[4][2];
#pragma unroll
            for (int nt=0;nt<4;nt++){
                bf[nt][0] = Bb[(nt*8)*ASTR + kb];
                bf[nt][1] = Bb[(nt*8)*ASTR + kb + 4];
            }
#pragma unroll
            for (int mt=0;mt<4;mt++){
#pragma unroll
                for (int nt=0;nt<4;nt++){
                    asm volatile(
                        "mma.sync.aligned.m16n8k8.row.col.f32.tf32.tf32.f32 "
                        "{%0,%1,%2,%3}, {%4,%5,%6,%7}, {%8,%9}, {%0,%1,%2,%3};"
                        : "+f"(acc[mt][nt][0]), "+f"(acc[mt][nt][1]),
                          "+f"(acc[mt][nt][2]), "+f"(acc[mt][nt][3])
                        : "r"(af[mt][0]), "r"(af[mt][1]), "r"(af[mt][2]), "r"(af[mt][3]),
                          "r"(bf[nt][0]), "r"(bf[nt][1]));
                }
            }
        }
    }

    int q = q0 + warpM;
#pragma unroll
    for (int nt=0; nt<4; nt++){
#pragma unroll
        for (int hc=0; hc<2; hc++){
            int col = nh*128 + n0l + nt*8 + 2*tig + hc;
            float bias = __ldg(&b2[col]);
            float mx=-3.402823466e38f, mn=3.402823466e38f, sum=0.f, sq=0.f;
#pragma unroll
            for (int mt=0;mt<4;mt++){
                float h0 = acc[mt][nt][hc]   + bias;
                float h1 = acc[mt][nt][2+hc] + bias;
                mx=fmaxf(mx,fmaxf(h0,h1)); mn=fminf(mn,fminf(h0,h1));
                sum += h0 + h1; sq = fmaf(h0,h0,sq); sq = fmaf(h1,h1,sq);
            }
#pragma unroll
            for (int off=4; off<=16; off<<=1){
                mx  = fmaxf(mx,  __shfl_xor_sync(0xffffffffu, mx,  off));
                mn  = fminf(mn,  __shfl_xor_sync(0xffffffffu, mn,  off));
                sum = sum +      __shfl_xor_sync(0xffffffffu, sum, off);
                sq  = sq +       __shfl_xor_sync(0xffffffffu, sq,  off);
            }
            if (g == 0){
                g_mx[(size_t)q*CC + col] = mx;
                g_mn[(size_t)q*CC + col] = mn;
                atomicAdd(&g_sum2[col], sum);
                atomicAdd(&g_sq2[col],  sq);
            }
        }
    }
}

// ---------------- BN2 + ReLU + maxpool + outputs ----------------
__global__ __launch_bounds__(256) void k_out(const float* __restrict__ pos,
                                             const float* __restrict__ gamma2,
                                             const float* __restrict__ beta2,
                                             float* __restrict__ out){
    int q = blockIdx.x, t = threadIdx.x, b = q/SS;
    int o = t;
    float mean = g_sum2[o]*(1.0f/MTOT);
    float var  = g_sq2[o]*(1.0f/MTOT) - mean*mean;
    float a    = gamma2[o]*rsqrtf(var + EPSF);
    float cc   = beta2[o] - mean*a;
    float v = (a>=0.f) ? fmaf(a, g_mx[(size_t)q*CC+o], cc)
                       : fmaf(a, g_mn[(size_t)q*CC+o], cc);
    out[(size_t)BB*SS*3 + (size_t)q*CC + o] = fmaxf(v, 0.f);
    if (t < 3){
        int cent = g_cent[q];
        out[(size_t)q*3 + t] = pos[(size_t)(b*NN + cent)*3 + t];
    }
}

// ---------------- launch ----------------
extern "C" void kernel_launch(void* const* d_in, const int* in_sizes, int n_in,
                              void* d_out, int out_size){
    const float* pos    = (const float*)d_in[0];
    const float* feat   = (const float*)d_in[1];
    const float* W1     = (const float*)d_in[2];
    const float* b1     = (const float*)d_in[3];
    const float* gamma1 = (const float*)d_in[4];
    const float* beta1  = (const float*)d_in[5];
    const float* W2     = (const float*)d_in[6];
    const float* b2     = (const float*)d_in[7];
    const float* gamma2 = (const float*)d_in[8];
    const float* beta2  = (const float*)d_in[9];
    float* out = (float*)d_out;

    const int mega1_smem = 128 + NN*3*4 + SS*4 + (NN/32)*4 + 64;          // ~54 KB
    const int gemm2_smem = (128 + 128) * ASTR * sizeof(float);            // 36864 B
    cudaFuncSetAttribute(k_mega1,  cudaFuncAttributeMaxDynamicSharedMemorySize, mega1_smem);
    cudaFuncSetAttribute(k_gemm2m, cudaFuncAttributeMaxDynamicSharedMemorySize, gemm2_smem);

    k_mega1 <<<4 + (BB*NN)/16 + 1, 256, mega1_smem>>>(pos, feat, W1, W2); // 1
    k_qgemm <<<(BB*SS)/16, 256>>>(feat, W1);                              // 2
    k_knns  <<<BB*SS, 256>>>(pos, b1);                                    // 3
    k_gemm2m<<<BB*SS, 256, gemm2_smem>>>(b1, gamma1, beta1, b2);          // 4 -> profiled
    k_out   <<<BB*SS, 256>>>(pos, gamma2, beta2, out);                    // 5
}